// round 5
// baseline (speedup 1.0000x reference)
#include <cuda_runtime.h>

#define MAX_N 100000
#define MAX_E 1600000
#define IN_F 128
#define EDGE_F 16
#define SCAN_BLK 1024
#define MAX_SCAN_BLOCKS 128   // ceil(100000/1024)=98

// ---------------- static device scratch (allocation-free rule) --------------
__device__ __align__(16) int  g_cnt[MAX_N];             // per-dst degree
__device__ __align__(16) int  g_off[MAX_N];             // CSR start offsets
__device__ __align__(16) int  g_cur[MAX_N];             // scatter cursors
__device__ __align__(16) int  g_bsum[MAX_SCAN_BLOCKS];  // per-scan-block sums
__device__ __align__(16) int  g_bbase[MAX_SCAN_BLOCKS]; // scanned block bases
__device__ __align__(16) int2 g_edges[MAX_E];           // (src, edge_id) bucketed by dst
__device__ __align__(16) float g_A[(size_t)MAX_N * IN_F]; // pre-MLP activations
__device__ int g_idx64;                                  // 1 if edge_index is int64

// ---------------------------------------------------------------------------
// 0) detect edge_index dtype: int64 little-endian small values have all-zero
//    high words. 128 random int32s in [0,100000) are never all zero.
__global__ void k_detect(const int* __restrict__ ei_raw) {
    if (blockIdx.x == 0 && threadIdx.x == 0) {
        int is64 = 1;
        for (int i = 1; i < 256; i += 2)
            if (ei_raw[i] != 0) { is64 = 0; break; }
        g_idx64 = is64;
    }
}

__device__ __forceinline__ int load_idx(const void* ei, size_t pos, int is64) {
    if (is64) return (int)(reinterpret_cast<const long long*>(ei)[pos]);
    return reinterpret_cast<const int*>(ei)[pos];
}

// ---------------------------------------------------------------------------
// 1) zero histogram
__global__ void k_zero(int N) {
    int i = blockIdx.x * blockDim.x + threadIdx.x;
    if (i < N) g_cnt[i] = 0;
}

// 2) histogram of dst
__global__ void k_hist(const void* __restrict__ ei, int E) {
    int e = blockIdx.x * blockDim.x + threadIdx.x;
    int is64 = g_idx64;
    if (e < E) {
        int dst = load_idx(ei, (size_t)E + e, is64);
        atomicAdd(&g_cnt[dst], 1);
    }
}

// 3) per-block exclusive scan (1024-wide), emit block sums
__global__ void k_scanA(int N) {
    __shared__ int s[SCAN_BLK];
    int t = threadIdx.x;
    int idx = blockIdx.x * SCAN_BLK + t;
    int v = (idx < N) ? g_cnt[idx] : 0;
    s[t] = v;
    __syncthreads();
    for (int off = 1; off < SCAN_BLK; off <<= 1) {
        int add = (t >= off) ? s[t - off] : 0;
        __syncthreads();
        s[t] += add;
        __syncthreads();
    }
    if (idx < N) g_off[idx] = s[t] - v;           // exclusive
    if (t == SCAN_BLK - 1) g_bsum[blockIdx.x] = s[t];
}

// 4) scan of block sums (single block of 128 threads)
__global__ void k_scanB(int nb) {
    __shared__ int s[MAX_SCAN_BLOCKS];
    int t = threadIdx.x;
    int v = (t < nb) ? g_bsum[t] : 0;
    s[t] = v;
    __syncthreads();
    for (int off = 1; off < MAX_SCAN_BLOCKS; off <<= 1) {
        int add = (t >= off) ? s[t - off] : 0;
        __syncthreads();
        s[t] += add;
        __syncthreads();
    }
    if (t < nb) g_bbase[t] = s[t] - v;            // exclusive
}

// 5) finalize offsets + init cursors
__global__ void k_initcur(int N) {
    int i = blockIdx.x * blockDim.x + threadIdx.x;
    if (i < N) {
        int base = g_off[i] + g_bbase[i >> 10];
        g_off[i] = base;
        g_cur[i] = base;
    }
}

// 6) ticket scatter: bucket edges by dst
__global__ void k_scatter(const void* __restrict__ ei, int E) {
    int e = blockIdx.x * blockDim.x + threadIdx.x;
    int is64 = g_idx64;
    if (e < E) {
        int src = load_idx(ei, (size_t)e, is64);
        int dst = load_idx(ei, (size_t)E + e, is64);
        int p = atomicAdd(&g_cur[dst], 1);
        g_edges[p] = make_int2(src, e);
    }
}

// ---------------------------------------------------------------------------
// 7) warp-per-node gather, fused:
//    A[n] = sum_{e->n} H[src(e)] + (sum_{e->n} edge_attr[e]) @ We + deg(n)*be
// ---------------------------------------------------------------------------
__global__ void __launch_bounds__(256)
k_gather(const float* __restrict__ H, const float* __restrict__ EA,
         const float* __restrict__ We, const float* __restrict__ be, int N) {
    int warp = (int)((blockIdx.x * (size_t)blockDim.x + threadIdx.x) >> 5);
    int lane = threadIdx.x & 31;
    if (warp >= N) return;

    int start = g_off[warp];
    int d = g_cnt[warp];

    float4 accH = make_float4(0.f, 0.f, 0.f, 0.f);
    float eaSum = 0.f;   // lane k<16 holds sum of edge_attr[:,k]

    const int2* ep = g_edges + start;
    for (int i = 0; i < d; i++) {
        int2 se = ep[i];                           // broadcast across warp
        const float4* hrow = reinterpret_cast<const float4*>(H + (size_t)se.x * IN_F);
        float4 hv = hrow[lane];
        accH.x += hv.x; accH.y += hv.y; accH.z += hv.z; accH.w += hv.w;
        if (lane < EDGE_F)
            eaSum += EA[(size_t)se.y * EDGE_F + lane];
    }

    // a = accH + eaSum @ We + deg * be   (features f = lane*4 .. lane*4+3)
    float4 a = accH;
    #pragma unroll
    for (int k = 0; k < EDGE_F; k++) {
        float ek = __shfl_sync(0xffffffffu, eaSum, k);
        float4 w = reinterpret_cast<const float4*>(We + k * IN_F)[lane];
        a.x += ek * w.x; a.y += ek * w.y; a.z += ek * w.z; a.w += ek * w.w;
    }
    float degf = (float)d;
    float4 bv = reinterpret_cast<const float4*>(be)[lane];
    a.x += degf * bv.x; a.y += degf * bv.y; a.z += degf * bv.z; a.w += degf * bv.w;

    reinterpret_cast<float4*>(g_A + (size_t)warp * IN_F)[lane] = a;
}

// ---------------------------------------------------------------------------
// 8) fused node MLP: out = relu(A@W1+b1)@W2 + b2
//    64-row tile, 256 threads, 4x8 microtile, W from global (L2/L1 resident).
// ---------------------------------------------------------------------------
#define MT_ROWS 64
#define AT_STRIDE 68   // 128 x 68 floats = 34,816 B static smem (16B-aligned rows)

__global__ void __launch_bounds__(256, 2)
k_mlp(const float* __restrict__ W1, const float* __restrict__ b1,
      const float* __restrict__ W2, const float* __restrict__ b2,
      float* __restrict__ out, int N) {
    __shared__ __align__(16) float sAT[128 * AT_STRIDE];  // A^T then h^T: [f/k][r]

    const int tid = threadIdx.x;
    const int n0 = blockIdx.x * MT_ROWS;

    // stage A^T (coalesced global reads)
    for (int i = tid; i < MT_ROWS * 128; i += 256) {
        int r = i >> 7, f = i & 127;
        int n = n0 + r;
        sAT[f * AT_STRIDE + r] = (n < N) ? g_A[(size_t)n * IN_F + f] : 0.f;
    }
    __syncthreads();

    const int tx = tid & 15;          // col group -> c0 = tx*8
    const int ty = tid >> 4;          // row group -> r0 = ty*4
    const int c0 = tx * 8;
    const int r0 = ty * 4;

    float acc[4][8];

    // ---- GEMM1: h = relu(A @ W1 + b1) ----
    #pragma unroll
    for (int j = 0; j < 8; j++) {
        float bj = b1[c0 + j];
        #pragma unroll
        for (int i = 0; i < 4; i++) acc[i][j] = bj;
    }

    #pragma unroll 4
    for (int k = 0; k < 128; k++) {
        float4 a4 = *reinterpret_cast<const float4*>(&sAT[k * AT_STRIDE + r0]);
        float4 w0 = *reinterpret_cast<const float4*>(W1 + k * 128 + c0);
        float4 w1v = *reinterpret_cast<const float4*>(W1 + k * 128 + c0 + 4);
        float a[4] = {a4.x, a4.y, a4.z, a4.w};
        float w[8] = {w0.x, w0.y, w0.z, w0.w, w1v.x, w1v.y, w1v.z, w1v.w};
        #pragma unroll
        for (int i = 0; i < 4; i++)
            #pragma unroll
            for (int j = 0; j < 8; j++)
                acc[i][j] = fmaf(a[i], w[j], acc[i][j]);
    }
    __syncthreads();   // all GEMM1 reads of sAT done

    // write h^T (with relu) back into sAT
    #pragma unroll
    for (int i = 0; i < 4; i++)
        #pragma unroll
        for (int j = 0; j < 8; j++)
            sAT[(c0 + j) * AT_STRIDE + (r0 + i)] = fmaxf(acc[i][j], 0.f);
    __syncthreads();

    // ---- GEMM2: out = h @ W2 + b2 ----
    #pragma unroll
    for (int j = 0; j < 8; j++) {
        float bj = b2[c0 + j];
        #pragma unroll
        for (int i = 0; i < 4; i++) acc[i][j] = bj;
    }

    #pragma unroll 4
    for (int k = 0; k < 128; k++) {
        float4 a4 = *reinterpret_cast<const float4*>(&sAT[k * AT_STRIDE + r0]);
        float4 w0 = *reinterpret_cast<const float4*>(W2 + k * 128 + c0);
        float4 w1v = *reinterpret_cast<const float4*>(W2 + k * 128 + c0 + 4);
        float a[4] = {a4.x, a4.y, a4.z, a4.w};
        float w[8] = {w0.x, w0.y, w0.z, w0.w, w1v.x, w1v.y, w1v.z, w1v.w};
        #pragma unroll
        for (int i = 0; i < 4; i++)
            #pragma unroll
            for (int j = 0; j < 8; j++)
                acc[i][j] = fmaf(a[i], w[j], acc[i][j]);
    }

    // epilogue
    #pragma unroll
    for (int i = 0; i < 4; i++) {
        int n = n0 + r0 + i;
        if (n < N) {
            float4 o0 = make_float4(acc[i][0], acc[i][1], acc[i][2], acc[i][3]);
            float4 o1 = make_float4(acc[i][4], acc[i][5], acc[i][6], acc[i][7]);
            float4* op = reinterpret_cast<float4*>(out + (size_t)n * 128 + c0);
            op[0] = o0;
            op[1] = o1;
        }
    }
}

// ---------------------------------------------------------------------------
extern "C" void kernel_launch(void* const* d_in, const int* in_sizes, int n_in,
                              void* d_out, int out_size) {
    const float* H  = (const float*)d_in[0];
    const void*  ei = d_in[1];                    // int32 or int64, detected on device
    const float* EA = (const float*)d_in[2];
    const float* We = (const float*)d_in[3];
    const float* be = (const float*)d_in[4];
    const float* W1 = (const float*)d_in[5];
    const float* b1 = (const float*)d_in[6];
    const float* W2 = (const float*)d_in[7];
    const float* b2 = (const float*)d_in[8];
    float* out = (float*)d_out;

    int N = in_sizes[0] / IN_F;
    int E = in_sizes[2] / EDGE_F;
    int nScanBlocks = (N + SCAN_BLK - 1) / SCAN_BLK;

    k_detect<<<1, 32>>>((const int*)ei);
    k_zero<<<(N + 255) / 256, 256>>>(N);
    k_hist<<<(E + 255) / 256, 256>>>(ei, E);
    k_scanA<<<nScanBlocks, SCAN_BLK>>>(N);
    k_scanB<<<1, MAX_SCAN_BLOCKS>>>(nScanBlocks);
    k_initcur<<<(N + 255) / 256, 256>>>(N);
    k_scatter<<<(E + 255) / 256, 256>>>(ei, E);

    int gblocks = (N + 7) / 8;   // 8 warps (256 threads) per block
    k_gather<<<gblocks, 256>>>(H, EA, We, be, N);

    k_mlp<<<(N + MT_ROWS - 1) / MT_ROWS, 256>>>(W1, b1, W2, b2, out, N);
}

// round 6
// speedup vs baseline: 1.0227x; 1.0227x over previous
#include <cuda_runtime.h>

#define MAX_N 100000
#define MAX_E 1600000
#define IN_F 128
#define EDGE_F 16
#define SCAN_BLK 1024
#define MAX_SCAN_BLOCKS 128   // ceil(100000/1024)=98

// ---------------- static device scratch (allocation-free rule) --------------
__device__ __align__(16) int  g_cnt[MAX_N];             // per-dst degree
__device__ __align__(16) int  g_off[MAX_N];             // CSR start offsets
__device__ __align__(16) int  g_cur[MAX_N];             // scatter cursors
__device__ __align__(16) int  g_bsum[MAX_SCAN_BLOCKS];  // per-scan-block sums
__device__ __align__(16) int  g_bbase[MAX_SCAN_BLOCKS]; // scanned block bases
__device__ __align__(16) int2 g_edges[MAX_E];           // (src, edge_id) bucketed by dst
__device__ __align__(16) float g_A[(size_t)MAX_N * IN_F]; // pre-MLP activations
__device__ int g_idx64;                                  // 1 if edge_index is int64

typedef unsigned long long u64t;

__device__ __forceinline__ u64t pack_dup(float x) {
    u64t r; asm("mov.b64 %0, {%1, %1};" : "=l"(r) : "f"(x)); return r;
}
__device__ __forceinline__ void fma2(u64t& acc, u64t a, u64t b) {
    asm("fma.rn.f32x2 %0, %1, %2, %0;" : "+l"(acc) : "l"(a), "l"(b));
}
__device__ __forceinline__ float2 unpk(u64t v) {
    float2 f; asm("mov.b64 {%0, %1}, %2;" : "=f"(f.x), "=f"(f.y) : "l"(v)); return f;
}

// ---------------------------------------------------------------------------
// 0) detect edge_index dtype (int64 small values -> all-zero high words)
__global__ void k_detect(const int* __restrict__ ei_raw) {
    if (blockIdx.x == 0 && threadIdx.x == 0) {
        int is64 = 1;
        for (int i = 1; i < 256; i += 2)
            if (ei_raw[i] != 0) { is64 = 0; break; }
        g_idx64 = is64;
    }
}

__device__ __forceinline__ int load_idx(const void* ei, size_t pos, int is64) {
    if (is64) return (int)(reinterpret_cast<const long long*>(ei)[pos]);
    return reinterpret_cast<const int*>(ei)[pos];
}

// ---------------------------------------------------------------------------
__global__ void k_zero(int N) {
    int i = blockIdx.x * blockDim.x + threadIdx.x;
    if (i < N) g_cnt[i] = 0;
}

__global__ void k_hist(const void* __restrict__ ei, int E) {
    int e = blockIdx.x * blockDim.x + threadIdx.x;
    int is64 = g_idx64;
    if (e < E) {
        int dst = load_idx(ei, (size_t)E + e, is64);
        atomicAdd(&g_cnt[dst], 1);
    }
}

__global__ void k_scanA(int N) {
    __shared__ int s[SCAN_BLK];
    int t = threadIdx.x;
    int idx = blockIdx.x * SCAN_BLK + t;
    int v = (idx < N) ? g_cnt[idx] : 0;
    s[t] = v;
    __syncthreads();
    for (int off = 1; off < SCAN_BLK; off <<= 1) {
        int add = (t >= off) ? s[t - off] : 0;
        __syncthreads();
        s[t] += add;
        __syncthreads();
    }
    if (idx < N) g_off[idx] = s[t] - v;           // exclusive
    if (t == SCAN_BLK - 1) g_bsum[blockIdx.x] = s[t];
}

__global__ void k_scanB(int nb) {
    __shared__ int s[MAX_SCAN_BLOCKS];
    int t = threadIdx.x;
    int v = (t < nb) ? g_bsum[t] : 0;
    s[t] = v;
    __syncthreads();
    for (int off = 1; off < MAX_SCAN_BLOCKS; off <<= 1) {
        int add = (t >= off) ? s[t - off] : 0;
        __syncthreads();
        s[t] += add;
        __syncthreads();
    }
    if (t < nb) g_bbase[t] = s[t] - v;            // exclusive
}

__global__ void k_initcur(int N) {
    int i = blockIdx.x * blockDim.x + threadIdx.x;
    if (i < N) {
        int base = g_off[i] + g_bbase[i >> 10];
        g_off[i] = base;
        g_cur[i] = base;
    }
}

__global__ void k_scatter(const void* __restrict__ ei, int E) {
    int e = blockIdx.x * blockDim.x + threadIdx.x;
    int is64 = g_idx64;
    if (e < E) {
        int src = load_idx(ei, (size_t)e, is64);
        int dst = load_idx(ei, (size_t)E + e, is64);
        int p = atomicAdd(&g_cur[dst], 1);
        g_edges[p] = make_int2(src, e);
    }
}

// ---------------------------------------------------------------------------
// 7) warp-per-node gather, fused:
//    A[n] = sum_{e->n} H[src(e)] + (sum_{e->n} edge_attr[e]) @ We + deg(n)*be
// ---------------------------------------------------------------------------
__global__ void __launch_bounds__(256)
k_gather(const float* __restrict__ H, const float* __restrict__ EA,
         const float* __restrict__ We, const float* __restrict__ be, int N) {
    int warp = (int)((blockIdx.x * (size_t)blockDim.x + threadIdx.x) >> 5);
    int lane = threadIdx.x & 31;
    if (warp >= N) return;

    int start = g_off[warp];
    int d = g_cnt[warp];

    float4 accH = make_float4(0.f, 0.f, 0.f, 0.f);
    float eaSum = 0.f;   // lane k<16 holds sum of edge_attr[:,k]

    const int2* ep = g_edges + start;
    for (int i = 0; i < d; i++) {
        int2 se = ep[i];                           // broadcast across warp
        const float4* hrow = reinterpret_cast<const float4*>(H + (size_t)se.x * IN_F);
        float4 hv = hrow[lane];
        accH.x += hv.x; accH.y += hv.y; accH.z += hv.z; accH.w += hv.w;
        if (lane < EDGE_F)
            eaSum += EA[(size_t)se.y * EDGE_F + lane];
    }

    float4 a = accH;
    #pragma unroll
    for (int k = 0; k < EDGE_F; k++) {
        float ek = __shfl_sync(0xffffffffu, eaSum, k);
        float4 w = reinterpret_cast<const float4*>(We + k * IN_F)[lane];
        a.x += ek * w.x; a.y += ek * w.y; a.z += ek * w.z; a.w += ek * w.w;
    }
    float degf = (float)d;
    float4 bv = reinterpret_cast<const float4*>(be)[lane];
    a.x += degf * bv.x; a.y += degf * bv.y; a.z += degf * bv.z; a.w += degf * bv.w;

    reinterpret_cast<float4*>(g_A + (size_t)warp * IN_F)[lane] = a;
}

// ---------------------------------------------------------------------------
// 8) fused node MLP: out = relu(A@W1+b1)@W2 + b2
//    64-row tile, 256 threads, 4 rows x 8 cols microtile, packed f32x2 FMA.
// ---------------------------------------------------------------------------
#define MT_ROWS 64
#define AT_STRIDE 68   // 128 x 68 floats = 34,816 B static smem

__global__ void __launch_bounds__(256, 2)
k_mlp(const float* __restrict__ W1, const float* __restrict__ b1,
      const float* __restrict__ W2, const float* __restrict__ b2,
      float* __restrict__ out, int N) {
    __shared__ __align__(16) float sAT[128 * AT_STRIDE];  // A^T then h^T: [f/k][r]

    const int tid = threadIdx.x;
    const int n0 = blockIdx.x * MT_ROWS;

    // stage A^T (coalesced global reads)
    for (int i = tid; i < MT_ROWS * 128; i += 256) {
        int r = i >> 7, f = i & 127;
        int n = n0 + r;
        sAT[f * AT_STRIDE + r] = (n < N) ? g_A[(size_t)n * IN_F + f] : 0.f;
    }
    __syncthreads();

    const int tx = tid & 15;          // col group -> c0 = tx*8
    const int ty = tid >> 4;          // row group -> r0 = ty*4
    const int c0 = tx * 8;
    const int r0 = ty * 4;

    u64t acc[4][4];  // [row][colpair], each u64 = 2 adjacent output cols

    // ---- GEMM1: h = relu(A @ W1 + b1) ----
    {
        float4 bb0 = *reinterpret_cast<const float4*>(b1 + c0);
        float4 bb1 = *reinterpret_cast<const float4*>(b1 + c0 + 4);
        u64t bp0, bp1, bp2, bp3;
        asm("mov.b64 %0, {%1, %2};" : "=l"(bp0) : "f"(bb0.x), "f"(bb0.y));
        asm("mov.b64 %0, {%1, %2};" : "=l"(bp1) : "f"(bb0.z), "f"(bb0.w));
        asm("mov.b64 %0, {%1, %2};" : "=l"(bp2) : "f"(bb1.x), "f"(bb1.y));
        asm("mov.b64 %0, {%1, %2};" : "=l"(bp3) : "f"(bb1.z), "f"(bb1.w));
        #pragma unroll
        for (int i = 0; i < 4; i++) {
            acc[i][0] = bp0; acc[i][1] = bp1; acc[i][2] = bp2; acc[i][3] = bp3;
        }
    }

    #pragma unroll 4
    for (int k = 0; k < 128; k++) {
        float4 a4 = *reinterpret_cast<const float4*>(&sAT[k * AT_STRIDE + r0]);
        float4 w0 = *reinterpret_cast<const float4*>(W1 + k * 128 + c0);
        float4 w1v = *reinterpret_cast<const float4*>(W1 + k * 128 + c0 + 4);
        u64t wp0, wp1, wp2, wp3;
        asm("mov.b64 %0, {%1, %2};" : "=l"(wp0) : "f"(w0.x), "f"(w0.y));
        asm("mov.b64 %0, {%1, %2};" : "=l"(wp1) : "f"(w0.z), "f"(w0.w));
        asm("mov.b64 %0, {%1, %2};" : "=l"(wp2) : "f"(w1v.x), "f"(w1v.y));
        asm("mov.b64 %0, {%1, %2};" : "=l"(wp3) : "f"(w1v.z), "f"(w1v.w));
        u64t ad0 = pack_dup(a4.x), ad1 = pack_dup(a4.y),
             ad2 = pack_dup(a4.z), ad3 = pack_dup(a4.w);
        fma2(acc[0][0], ad0, wp0); fma2(acc[0][1], ad0, wp1);
        fma2(acc[0][2], ad0, wp2); fma2(acc[0][3], ad0, wp3);
        fma2(acc[1][0], ad1, wp0); fma2(acc[1][1], ad1, wp1);
        fma2(acc[1][2], ad1, wp2); fma2(acc[1][3], ad1, wp3);
        fma2(acc[2][0], ad2, wp0); fma2(acc[2][1], ad2, wp1);
        fma2(acc[2][2], ad2, wp2); fma2(acc[2][3], ad2, wp3);
        fma2(acc[3][0], ad3, wp0); fma2(acc[3][1], ad3, wp1);
        fma2(acc[3][2], ad3, wp2); fma2(acc[3][3], ad3, wp3);
    }
    __syncthreads();   // all GEMM1 reads of sAT done

    // write h^T (relu) back into sAT
    #pragma unroll
    for (int i = 0; i < 4; i++) {
        #pragma unroll
        for (int jj = 0; jj < 4; jj++) {
            float2 v = unpk(acc[i][jj]);
            sAT[(c0 + 2 * jj) * AT_STRIDE + r0 + i]     = fmaxf(v.x, 0.f);
            sAT[(c0 + 2 * jj + 1) * AT_STRIDE + r0 + i] = fmaxf(v.y, 0.f);
        }
    }
    __syncthreads();

    // ---- GEMM2: out = h @ W2 + b2 ----
    {
        float4 bb0 = *reinterpret_cast<const float4*>(b2 + c0);
        float4 bb1 = *reinterpret_cast<const float4*>(b2 + c0 + 4);
        u64t bp0, bp1, bp2, bp3;
        asm("mov.b64 %0, {%1, %2};" : "=l"(bp0) : "f"(bb0.x), "f"(bb0.y));
        asm("mov.b64 %0, {%1, %2};" : "=l"(bp1) : "f"(bb0.z), "f"(bb0.w));
        asm("mov.b64 %0, {%1, %2};" : "=l"(bp2) : "f"(bb1.x), "f"(bb1.y));
        asm("mov.b64 %0, {%1, %2};" : "=l"(bp3) : "f"(bb1.z), "f"(bb1.w));
        #pragma unroll
        for (int i = 0; i < 4; i++) {
            acc[i][0] = bp0; acc[i][1] = bp1; acc[i][2] = bp2; acc[i][3] = bp3;
        }
    }

    #pragma unroll 4
    for (int k = 0; k < 128; k++) {
        float4 a4 = *reinterpret_cast<const float4*>(&sAT[k * AT_STRIDE + r0]);
        float4 w0 = *reinterpret_cast<const float4*>(W2 + k * 128 + c0);
        float4 w1v = *reinterpret_cast<const float4*>(W2 + k * 128 + c0 + 4);
        u64t wp0, wp1, wp2, wp3;
        asm("mov.b64 %0, {%1, %2};" : "=l"(wp0) : "f"(w0.x), "f"(w0.y));
        asm("mov.b64 %0, {%1, %2};" : "=l"(wp1) : "f"(w0.z), "f"(w0.w));
        asm("mov.b64 %0, {%1, %2};" : "=l"(wp2) : "f"(w1v.x), "f"(w1v.y));
        asm("mov.b64 %0, {%1, %2};" : "=l"(wp3) : "f"(w1v.z), "f"(w1v.w));
        u64t ad0 = pack_dup(a4.x), ad1 = pack_dup(a4.y),
             ad2 = pack_dup(a4.z), ad3 = pack_dup(a4.w);
        fma2(acc[0][0], ad0, wp0); fma2(acc[0][1], ad0, wp1);
        fma2(acc[0][2], ad0, wp2); fma2(acc[0][3], ad0, wp3);
        fma2(acc[1][0], ad1, wp0); fma2(acc[1][1], ad1, wp1);
        fma2(acc[1][2], ad1, wp2); fma2(acc[1][3], ad1, wp3);
        fma2(acc[2][0], ad2, wp0); fma2(acc[2][1], ad2, wp1);
        fma2(acc[2][2], ad2, wp2); fma2(acc[2][3], ad2, wp3);
        fma2(acc[3][0], ad3, wp0); fma2(acc[3][1], ad3, wp1);
        fma2(acc[3][2], ad3, wp2); fma2(acc[3][3], ad3, wp3);
    }

    // epilogue
    #pragma unroll
    for (int i = 0; i < 4; i++) {
        int n = n0 + r0 + i;
        if (n < N) {
            float2 p0 = unpk(acc[i][0]), p1 = unpk(acc[i][1]);
            float2 p2 = unpk(acc[i][2]), p3 = unpk(acc[i][3]);
            float4* op = reinterpret_cast<float4*>(out + (size_t)n * 128 + c0);
            op[0] = make_float4(p0.x, p0.y, p1.x, p1.y);
            op[1] = make_float4(p2.x, p2.y, p3.x, p3.y);
        }
    }
}

// ---------------------------------------------------------------------------
extern "C" void kernel_launch(void* const* d_in, const int* in_sizes, int n_in,
                              void* d_out, int out_size) {
    const float* H  = (const float*)d_in[0];
    const void*  ei = d_in[1];                    // int32 or int64, detected on device
    const float* EA = (const float*)d_in[2];
    const float* We = (const float*)d_in[3];
    const float* be = (const float*)d_in[4];
    const float* W1 = (const float*)d_in[5];
    const float* b1 = (const float*)d_in[6];
    const float* W2 = (const float*)d_in[7];
    const float* b2 = (const float*)d_in[8];
    float* out = (float*)d_out;

    int N = in_sizes[0] / IN_F;
    int E = in_sizes[2] / EDGE_F;
    int nScanBlocks = (N + SCAN_BLK - 1) / SCAN_BLK;

    k_detect<<<1, 32>>>((const int*)ei);
    k_zero<<<(N + 255) / 256, 256>>>(N);
    k_hist<<<(E + 255) / 256, 256>>>(ei, E);
    k_scanA<<<nScanBlocks, SCAN_BLK>>>(N);
    k_scanB<<<1, MAX_SCAN_BLOCKS>>>(nScanBlocks);
    k_initcur<<<(N + 255) / 256, 256>>>(N);
    k_scatter<<<(E + 255) / 256, 256>>>(ei, E);

    int gblocks = (N + 7) / 8;   // 8 warps (256 threads) per block
    k_gather<<<gblocks, 256>>>(H, EA, We, be, N);

    k_mlp<<<(N + MT_ROWS - 1) / MT_ROWS, 256>>>(W1, b1, W2, b2, out, N);
}

// round 7
// speedup vs baseline: 1.2483x; 1.2205x over previous
#include <cuda_runtime.h>
#include <cuda_bf16.h>

#define MAX_N 100000
#define MAX_E 1600000
#define IN_F 128
#define EDGE_F 16
#define SCAN_BLK 1024
#define MAX_SCAN_BLOCKS 128
#define N_PAD (MAX_N + 64)

// ---------------- static device scratch (allocation-free rule) --------------
__device__ __align__(16) int  g_cnt[MAX_N];
__device__ __align__(16) int  g_off[MAX_N];
__device__ __align__(16) int  g_cur[MAX_N];
__device__ __align__(16) int  g_bsum[MAX_SCAN_BLOCKS];
__device__ __align__(16) int  g_bbase[MAX_SCAN_BLOCKS];
__device__ __align__(16) int2 g_edges[MAX_E];
__device__ __align__(16) __nv_bfloat16 g_Ah[(size_t)N_PAD * IN_F];  // A hi
__device__ __align__(16) __nv_bfloat16 g_Al[(size_t)N_PAD * IN_F];  // A lo
__device__ __align__(16) __nv_bfloat16 g_W1h[IN_F * IN_F];  // [n][k] transposed
__device__ __align__(16) __nv_bfloat16 g_W1l[IN_F * IN_F];
__device__ __align__(16) __nv_bfloat16 g_W2h[IN_F * IN_F];
__device__ __align__(16) __nv_bfloat16 g_W2l[IN_F * IN_F];
__device__ int g_idx64;

// ------------------------------- helpers ------------------------------------
__device__ __forceinline__ unsigned cvt_bf16x2(float hi, float lo) {
    unsigned r; asm("cvt.rn.bf16x2.f32 %0, %1, %2;" : "=r"(r) : "f"(hi), "f"(lo));
    return r;
}
__device__ __forceinline__ float bflo_f(unsigned p) { return __uint_as_float(p << 16); }
__device__ __forceinline__ float bfhi_f(unsigned p) { return __uint_as_float(p & 0xffff0000u); }

__device__ __forceinline__ void mma16816(float c[4],
                                         unsigned a0, unsigned a1, unsigned a2, unsigned a3,
                                         unsigned b0, unsigned b1) {
    asm volatile(
        "mma.sync.aligned.m16n8k16.row.col.f32.bf16.bf16.f32 "
        "{%0,%1,%2,%3}, {%4,%5,%6,%7}, {%8,%9}, {%0,%1,%2,%3};"
        : "+f"(c[0]), "+f"(c[1]), "+f"(c[2]), "+f"(c[3])
        : "r"(a0), "r"(a1), "r"(a2), "r"(a3), "r"(b0), "r"(b1));
}

// ---------------------------------------------------------------------------
// 0) detect edge_index dtype (int64 small values -> all-zero high words)
__global__ void k_detect(const int* __restrict__ ei_raw) {
    if (blockIdx.x == 0 && threadIdx.x == 0) {
        int is64 = 1;
        for (int i = 1; i < 256; i += 2)
            if (ei_raw[i] != 0) { is64 = 0; break; }
        g_idx64 = is64;
    }
}

__device__ __forceinline__ int load_idx(const void* ei, size_t pos, int is64) {
    if (is64) return (int)(reinterpret_cast<const long long*>(ei)[pos]);
    return reinterpret_cast<const int*>(ei)[pos];
}

// ---------------------------------------------------------------------------
__global__ void k_zero(int N) {
    int i = blockIdx.x * blockDim.x + threadIdx.x;
    if (i < N) g_cnt[i] = 0;
}

__global__ void k_hist(const void* __restrict__ ei, int E) {
    int e = blockIdx.x * blockDim.x + threadIdx.x;
    int is64 = g_idx64;
    if (e < E) {
        int dst = load_idx(ei, (size_t)E + e, is64);
        atomicAdd(&g_cnt[dst], 1);
    }
}

__global__ void k_scanA(int N) {
    __shared__ int s[SCAN_BLK];
    int t = threadIdx.x;
    int idx = blockIdx.x * SCAN_BLK + t;
    int v = (idx < N) ? g_cnt[idx] : 0;
    s[t] = v;
    __syncthreads();
    for (int off = 1; off < SCAN_BLK; off <<= 1) {
        int add = (t >= off) ? s[t - off] : 0;
        __syncthreads();
        s[t] += add;
        __syncthreads();
    }
    if (idx < N) g_off[idx] = s[t] - v;
    if (t == SCAN_BLK - 1) g_bsum[blockIdx.x] = s[t];
}

__global__ void k_scanB(int nb) {
    __shared__ int s[MAX_SCAN_BLOCKS];
    int t = threadIdx.x;
    int v = (t < nb) ? g_bsum[t] : 0;
    s[t] = v;
    __syncthreads();
    for (int off = 1; off < MAX_SCAN_BLOCKS; off <<= 1) {
        int add = (t >= off) ? s[t - off] : 0;
        __syncthreads();
        s[t] += add;
        __syncthreads();
    }
    if (t < nb) g_bbase[t] = s[t] - v;
}

__global__ void k_initcur(int N) {
    int i = blockIdx.x * blockDim.x + threadIdx.x;
    if (i < N) {
        int base = g_off[i] + g_bbase[i >> 10];
        g_off[i] = base;
        g_cur[i] = base;
    }
}

__global__ void k_scatter(const void* __restrict__ ei, int E) {
    int e = blockIdx.x * blockDim.x + threadIdx.x;
    int is64 = g_idx64;
    if (e < E) {
        int src = load_idx(ei, (size_t)e, is64);
        int dst = load_idx(ei, (size_t)E + e, is64);
        int p = atomicAdd(&g_cur[dst], 1);
        g_edges[p] = make_int2(src, e);
    }
}

// ---------------------------------------------------------------------------
// W split + transpose: g_W*h/l[n][k] = bf16 split of W*[k][n]
__global__ void k_wsplit(const float* __restrict__ W1, const float* __restrict__ W2) {
    int i = blockIdx.x * blockDim.x + threadIdx.x;
    if (i < IN_F * IN_F) {
        int n = i >> 7, k = i & 127;
        float w = W1[k * IN_F + n];
        __nv_bfloat16 h = __float2bfloat16(w);
        g_W1h[i] = h;
        g_W1l[i] = __float2bfloat16(w - __bfloat162float(h));
        w = W2[k * IN_F + n];
        h = __float2bfloat16(w);
        g_W2h[i] = h;
        g_W2l[i] = __float2bfloat16(w - __bfloat162float(h));
    }
}

// ---------------------------------------------------------------------------
// warp-per-node gather -> writes split-bf16 activations
__global__ void __launch_bounds__(256)
k_gather(const float* __restrict__ H, const float* __restrict__ EA,
         const float* __restrict__ We, const float* __restrict__ be, int N) {
    int warp = (int)((blockIdx.x * (size_t)blockDim.x + threadIdx.x) >> 5);
    int lane = threadIdx.x & 31;
    if (warp >= N) return;

    int start = g_off[warp];
    int d = g_cnt[warp];

    float4 accH = make_float4(0.f, 0.f, 0.f, 0.f);
    float eaSum = 0.f;

    const int2* ep = g_edges + start;
    for (int i = 0; i < d; i++) {
        int2 se = ep[i];
        const float4* hrow = reinterpret_cast<const float4*>(H + (size_t)se.x * IN_F);
        float4 hv = hrow[lane];
        accH.x += hv.x; accH.y += hv.y; accH.z += hv.z; accH.w += hv.w;
        if (lane < EDGE_F)
            eaSum += EA[(size_t)se.y * EDGE_F + lane];
    }

    float4 a = accH;
    #pragma unroll
    for (int k = 0; k < EDGE_F; k++) {
        float ek = __shfl_sync(0xffffffffu, eaSum, k);
        float4 w = reinterpret_cast<const float4*>(We + k * IN_F)[lane];
        a.x += ek * w.x; a.y += ek * w.y; a.z += ek * w.z; a.w += ek * w.w;
    }
    float degf = (float)d;
    float4 bv = reinterpret_cast<const float4*>(be)[lane];
    a.x += degf * bv.x; a.y += degf * bv.y; a.z += degf * bv.z; a.w += degf * bv.w;

    // split to bf16 hi/lo, store 8B each
    unsigned ph0 = cvt_bf16x2(a.y, a.x);
    unsigned ph1 = cvt_bf16x2(a.w, a.z);
    unsigned pl0 = cvt_bf16x2(a.y - bfhi_f(ph0), a.x - bflo_f(ph0));
    unsigned pl1 = cvt_bf16x2(a.w - bfhi_f(ph1), a.z - bflo_f(ph1));

    size_t base = (size_t)warp * IN_F + lane * 4;
    *reinterpret_cast<uint2*>(g_Ah + base) = make_uint2(ph0, ph1);
    *reinterpret_cast<uint2*>(g_Al + base) = make_uint2(pl0, pl1);
}

// ---------------------------------------------------------------------------
// Tensor-core MLP: out = relu(A@W1+b1)@W2 + b2, split-bf16 3-term MMA.
// Block = 64 rows / 4 warps. Warp owns 16 rows x 128 cols. Zero smem.
// ---------------------------------------------------------------------------
__global__ void __launch_bounds__(128)
k_mma(const float* __restrict__ b1, const float* __restrict__ b2,
      float* __restrict__ out, int N) {
    const int warp = threadIdx.x >> 5;
    const int lane = threadIdx.x & 31;
    const int g = lane >> 2;       // group 0..7 -> row within tile
    const int t = lane & 3;        // thread-in-group -> col pair
    const int row0 = blockIdx.x * 64 + warp * 16;

    float c[16][4];   // 16 n-tiles (n8) covering 128 cols

    // ---- GEMM1: C = A @ W1 + b1 ----
    #pragma unroll
    for (int nt = 0; nt < 16; nt++) {
        float v0 = b1[nt * 8 + 2 * t], v1 = b1[nt * 8 + 2 * t + 1];
        c[nt][0] = v0; c[nt][1] = v1; c[nt][2] = v0; c[nt][3] = v1;
    }

    {
        const size_t rA = (size_t)(row0 + g) * IN_F;
        const size_t rB = (size_t)(row0 + g + 8) * IN_F;
        #pragma unroll
        for (int ks = 0; ks < 8; ks++) {
            int col = ks * 16 + 2 * t;
            unsigned ah0 = *reinterpret_cast<const unsigned*>(g_Ah + rA + col);
            unsigned ah1 = *reinterpret_cast<const unsigned*>(g_Ah + rB + col);
            unsigned ah2 = *reinterpret_cast<const unsigned*>(g_Ah + rA + col + 8);
            unsigned ah3 = *reinterpret_cast<const unsigned*>(g_Ah + rB + col + 8);
            unsigned al0 = *reinterpret_cast<const unsigned*>(g_Al + rA + col);
            unsigned al1 = *reinterpret_cast<const unsigned*>(g_Al + rB + col);
            unsigned al2 = *reinterpret_cast<const unsigned*>(g_Al + rA + col + 8);
            unsigned al3 = *reinterpret_cast<const unsigned*>(g_Al + rB + col + 8);
            #pragma unroll
            for (int nt = 0; nt < 16; nt++) {
                int wb = (nt * 8 + g) * IN_F + ks * 16 + 2 * t;
                unsigned bh0 = *reinterpret_cast<const unsigned*>(g_W1h + wb);
                unsigned bh1 = *reinterpret_cast<const unsigned*>(g_W1h + wb + 8);
                unsigned bl0 = *reinterpret_cast<const unsigned*>(g_W1l + wb);
                unsigned bl1 = *reinterpret_cast<const unsigned*>(g_W1l + wb + 8);
                mma16816(c[nt], ah0, ah1, ah2, ah3, bh0, bh1);
                mma16816(c[nt], al0, al1, al2, al3, bh0, bh1);
                mma16816(c[nt], ah0, ah1, ah2, ah3, bl0, bl1);
            }
        }
    }

    // ---- relu + in-register split to GEMM2 A-fragments ----
    unsigned hh[16][2], hl[16][2];
    #pragma unroll
    for (int nt = 0; nt < 16; nt++) {
        float r0 = fmaxf(c[nt][0], 0.f), r1 = fmaxf(c[nt][1], 0.f);
        float r2 = fmaxf(c[nt][2], 0.f), r3 = fmaxf(c[nt][3], 0.f);
        unsigned p0 = cvt_bf16x2(r1, r0);
        unsigned p1 = cvt_bf16x2(r3, r2);
        hh[nt][0] = p0;
        hh[nt][1] = p1;
        hl[nt][0] = cvt_bf16x2(r1 - bfhi_f(p0), r0 - bflo_f(p0));
        hl[nt][1] = cvt_bf16x2(r3 - bfhi_f(p1), r2 - bflo_f(p1));
    }

    // ---- GEMM2: C = h @ W2 + b2 ----
    #pragma unroll
    for (int nt = 0; nt < 16; nt++) {
        float v0 = b2[nt * 8 + 2 * t], v1 = b2[nt * 8 + 2 * t + 1];
        c[nt][0] = v0; c[nt][1] = v1; c[nt][2] = v0; c[nt][3] = v1;
    }

    #pragma unroll
    for (int ks = 0; ks < 8; ks++) {
        unsigned ah0 = hh[2 * ks][0],     ah1 = hh[2 * ks][1];
        unsigned ah2 = hh[2 * ks + 1][0], ah3 = hh[2 * ks + 1][1];
        unsigned al0 = hl[2 * ks][0],     al1 = hl[2 * ks][1];
        unsigned al2 = hl[2 * ks + 1][0], al3 = hl[2 * ks + 1][1];
        #pragma unroll
        for (int nt = 0; nt < 16; nt++) {
            int wb = (nt * 8 + g) * IN_F + ks * 16 + 2 * t;
            unsigned bh0 = *reinterpret_cast<const unsigned*>(g_W2h + wb);
            unsigned bh1 = *reinterpret_cast<const unsigned*>(g_W2h + wb + 8);
            unsigned bl0 = *reinterpret_cast<const unsigned*>(g_W2l + wb);
            unsigned bl1 = *reinterpret_cast<const unsigned*>(g_W2l + wb + 8);
            mma16816(c[nt], ah0, ah1, ah2, ah3, bh0, bh1);
            mma16816(c[nt], al0, al1, al2, al3, bh0, bh1);
            mma16816(c[nt], ah0, ah1, ah2, ah3, bl0, bl1);
        }
    }

    // ---- epilogue ----
    int rowA = row0 + g, rowB = row0 + g + 8;
    #pragma unroll
    for (int nt = 0; nt < 16; nt++) {
        int colp = nt * 8 + 2 * t;
        if (rowA < N)
            *reinterpret_cast<float2*>(out + (size_t)rowA * IN_F + colp) =
                make_float2(c[nt][0], c[nt][1]);
        if (rowB < N)
            *reinterpret_cast<float2*>(out + (size_t)rowB * IN_F + colp) =
                make_float2(c[nt][2], c[nt][3]);
    }
}

// ---------------------------------------------------------------------------
extern "C" void kernel_launch(void* const* d_in, const int* in_sizes, int n_in,
                              void* d_out, int out_size) {
    const float* H  = (const float*)d_in[0];
    const void*  ei = d_in[1];
    const float* EA = (const float*)d_in[2];
    const float* We = (const float*)d_in[3];
    const float* be = (const float*)d_in[4];
    const float* W1 = (const float*)d_in[5];
    const float* b1 = (const float*)d_in[6];
    const float* W2 = (const float*)d_in[7];
    const float* b2 = (const float*)d_in[8];
    float* out = (float*)d_out;

    int N = in_sizes[0] / IN_F;
    int E = in_sizes[2] / EDGE_F;
    int nScanBlocks = (N + SCAN_BLK - 1) / SCAN_BLK;

    k_detect<<<1, 32>>>((const int*)ei);
    k_wsplit<<<(IN_F * IN_F + 255) / 256, 256>>>(W1, W2);
    k_zero<<<(N + 255) / 256, 256>>>(N);
    k_hist<<<(E + 255) / 256, 256>>>(ei, E);
    k_scanA<<<nScanBlocks, SCAN_BLK>>>(N);
    k_scanB<<<1, MAX_SCAN_BLOCKS>>>(nScanBlocks);
    k_initcur<<<(N + 255) / 256, 256>>>(N);
    k_scatter<<<(E + 255) / 256, 256>>>(ei, E);

    int gblocks = (N + 7) / 8;
    k_gather<<<gblocks, 256>>>(H, EA, We, be, N);

    k_mma<<<(N + 63) / 64, 128>>>(b1, b2, out, N);
}

// round 10
// speedup vs baseline: 1.2549x; 1.0053x over previous
#include <cuda_runtime.h>
#include <cuda_bf16.h>

#define MAX_N 100000
#define MAX_E 1600000
#define IN_F 128
#define EDGE_F 16
#define SCAN_BLK 1024
#define MAX_SCAN_BLOCKS 128
#define N_PAD (MAX_N + 64)

// ---------------- static device scratch (allocation-free rule) --------------
__device__ __align__(16) int  g_cnt[MAX_N];
__device__ __align__(16) int  g_off[MAX_N];
__device__ __align__(16) int  g_cur[MAX_N];
__device__ __align__(16) int  g_bsum[MAX_SCAN_BLOCKS];
__device__ __align__(16) int  g_bbase[MAX_SCAN_BLOCKS];
__device__ __align__(16) int2 g_edges[MAX_E];
__device__ __align__(16) __nv_bfloat16 g_Ah[(size_t)N_PAD * IN_F];  // A hi
__device__ __align__(16) __nv_bfloat16 g_Al[(size_t)N_PAD * IN_F];  // A lo
__device__ __align__(16) __nv_bfloat16 g_W1h[IN_F * IN_F];  // [n][k] transposed
__device__ __align__(16) __nv_bfloat16 g_W1l[IN_F * IN_F];
__device__ __align__(16) __nv_bfloat16 g_W2h[IN_F * IN_F];
__device__ __align__(16) __nv_bfloat16 g_W2l[IN_F * IN_F];
__device__ int g_idx64;

// ------------------------------- helpers ------------------------------------
__device__ __forceinline__ unsigned cvt_bf16x2(float hi, float lo) {
    unsigned r; asm("cvt.rn.bf16x2.f32 %0, %1, %2;" : "=r"(r) : "f"(hi), "f"(lo));
    return r;
}
__device__ __forceinline__ float bflo_f(unsigned p) { return __uint_as_float(p << 16); }
__device__ __forceinline__ float bfhi_f(unsigned p) { return __uint_as_float(p & 0xffff0000u); }

__device__ __forceinline__ void mma16816(float c[4],
                                         unsigned a0, unsigned a1, unsigned a2, unsigned a3,
                                         unsigned b0, unsigned b1) {
    asm volatile(
        "mma.sync.aligned.m16n8k16.row.col.f32.bf16.bf16.f32 "
        "{%0,%1,%2,%3}, {%4,%5,%6,%7}, {%8,%9}, {%0,%1,%2,%3};"
        : "+f"(c[0]), "+f"(c[1]), "+f"(c[2]), "+f"(c[3])
        : "r"(a0), "r"(a1), "r"(a2), "r"(a3), "r"(b0), "r"(b1));
}

// ---------------------------------------------------------------------------
__global__ void k_detect(const int* __restrict__ ei_raw) {
    if (blockIdx.x == 0 && threadIdx.x == 0) {
        int is64 = 1;
        for (int i = 1; i < 256; i += 2)
            if (ei_raw[i] != 0) { is64 = 0; break; }
        g_idx64 = is64;
    }
}

__device__ __forceinline__ int load_idx(const void* ei, size_t pos, int is64) {
    if (is64) return (int)(reinterpret_cast<const long long*>(ei)[pos]);
    return reinterpret_cast<const int*>(ei)[pos];
}

// ---------------------------------------------------------------------------
__global__ void k_zero(int N) {
    int i = blockIdx.x * blockDim.x + threadIdx.x;
    if (i < N) g_cnt[i] = 0;
}

__global__ void k_hist(const void* __restrict__ ei, int E) {
    int e = blockIdx.x * blockDim.x + threadIdx.x;
    int is64 = g_idx64;
    if (e < E) {
        int dst = load_idx(ei, (size_t)E + e, is64);
        atomicAdd(&g_cnt[dst], 1);
    }
}

__global__ void k_scanA(int N) {
    __shared__ int s[SCAN_BLK];
    int t = threadIdx.x;
    int idx = blockIdx.x * SCAN_BLK + t;
    int v = (idx < N) ? g_cnt[idx] : 0;
    s[t] = v;
    __syncthreads();
    for (int off = 1; off < SCAN_BLK; off <<= 1) {
        int add = (t >= off) ? s[t - off] : 0;
        __syncthreads();
        s[t] += add;
        __syncthreads();
    }
    if (idx < N) g_off[idx] = s[t] - v;
    if (t == SCAN_BLK - 1) g_bsum[blockIdx.x] = s[t];
}

__global__ void k_scanB(int nb) {
    __shared__ int s[MAX_SCAN_BLOCKS];
    int t = threadIdx.x;
    int v = (t < nb) ? g_bsum[t] : 0;
    s[t] = v;
    __syncthreads();
    for (int off = 1; off < MAX_SCAN_BLOCKS; off <<= 1) {
        int add = (t >= off) ? s[t - off] : 0;
        __syncthreads();
        s[t] += add;
        __syncthreads();
    }
    if (t < nb) g_bbase[t] = s[t] - v;
}

__global__ void k_initcur(int N) {
    int i = blockIdx.x * blockDim.x + threadIdx.x;
    if (i < N) {
        int base = g_off[i] + g_bbase[i >> 10];
        g_off[i] = base;
        g_cur[i] = base;
    }
}

__global__ void k_scatter(const void* __restrict__ ei, int E) {
    int e = blockIdx.x * blockDim.x + threadIdx.x;
    int is64 = g_idx64;
    if (e < E) {
        int src = load_idx(ei, (size_t)e, is64);
        int dst = load_idx(ei, (size_t)E + e, is64);
        int p = atomicAdd(&g_cur[dst], 1);
        g_edges[p] = make_int2(src, e);
    }
}

// ---------------------------------------------------------------------------
__global__ void k_wsplit(const float* __restrict__ W1, const float* __restrict__ W2) {
    int i = blockIdx.x * blockDim.x + threadIdx.x;
    if (i < IN_F * IN_F) {
        int n = i >> 7, k = i & 127;
        float w = W1[k * IN_F + n];
        __nv_bfloat16 h = __float2bfloat16(w);
        g_W1h[i] = h;
        g_W1l[i] = __float2bfloat16(w - __bfloat162float(h));
        w = W2[k * IN_F + n];
        h = __float2bfloat16(w);
        g_W2h[i] = h;
        g_W2l[i] = __float2bfloat16(w - __bfloat162float(h));
    }
}

// ---------------------------------------------------------------------------
// warp-per-node gather, 4-edge unrolled for MLP, writes split-bf16 activations
// ---------------------------------------------------------------------------
__global__ void __launch_bounds__(256)
k_gather(const float* __restrict__ H, const float* __restrict__ EA,
         const float* __restrict__ We, const float* __restrict__ be, int N) {
    int warp = (int)((blockIdx.x * (size_t)blockDim.x + threadIdx.x) >> 5);
    int lane = threadIdx.x & 31;
    if (warp >= N) return;

    int start = g_off[warp];
    int d = g_cnt[warp];

    float4 accH = make_float4(0.f, 0.f, 0.f, 0.f);
    float eaSum = 0.f;   // lane k<16 holds sum of edge_attr[:,k]

    const int2* ep = g_edges + start;
    const float4* H4 = reinterpret_cast<const float4*>(H);

    int i = 0;
    for (; i + 4 <= d; i += 4) {
        // 4 independent edge records
        int2 e0 = ep[i], e1 = ep[i + 1], e2 = ep[i + 2], e3 = ep[i + 3];
        // 4 independent H-row loads (512B each, MLP=4)
        float4 h0 = H4[(size_t)e0.x * 32 + lane];
        float4 h1 = H4[(size_t)e1.x * 32 + lane];
        float4 h2 = H4[(size_t)e2.x * 32 + lane];
        float4 h3 = H4[(size_t)e3.x * 32 + lane];
        // 4 independent EA loads (lanes 0-15)
        float a0 = 0.f, a1 = 0.f, a2 = 0.f, a3 = 0.f;
        if (lane < EDGE_F) {
            a0 = EA[(size_t)e0.y * EDGE_F + lane];
            a1 = EA[(size_t)e1.y * EDGE_F + lane];
            a2 = EA[(size_t)e2.y * EDGE_F + lane];
            a3 = EA[(size_t)e3.y * EDGE_F + lane];
        }
        accH.x += (h0.x + h1.x) + (h2.x + h3.x);
        accH.y += (h0.y + h1.y) + (h2.y + h3.y);
        accH.z += (h0.z + h1.z) + (h2.z + h3.z);
        accH.w += (h0.w + h1.w) + (h2.w + h3.w);
        eaSum += (a0 + a1) + (a2 + a3);
    }
    for (; i < d; i++) {
        int2 se = ep[i];
        float4 hv = H4[(size_t)se.x * 32 + lane];
        accH.x += hv.x; accH.y += hv.y; accH.z += hv.z; accH.w += hv.w;
        if (lane < EDGE_F)
            eaSum += EA[(size_t)se.y * EDGE_F + lane];
    }

    float4 a = accH;
    #pragma unroll
    for (int k = 0; k < EDGE_F; k++) {
        float ek = __shfl_sync(0xffffffffu, eaSum, k);
        float4 w = reinterpret_cast<const float4*>(We + k * IN_F)[lane];
        a.x += ek * w.x; a.y += ek * w.y; a.z += ek * w.z; a.w += ek * w.w;
    }
    float degf = (float)d;
    float4 bv = reinterpret_cast<const float4*>(be)[lane];
    a.x += degf * bv.x; a.y += degf * bv.y; a.z += degf * bv.z; a.w += degf * bv.w;

    // split to bf16 hi/lo, store 8B each
    unsigned ph0 = cvt_bf16x2(a.y, a.x);
    unsigned ph1 = cvt_bf16x2(a.w, a.z);
    unsigned pl0 = cvt_bf16x2(a.y - bfhi_f(ph0), a.x - bflo_f(ph0));
    unsigned pl1 = cvt_bf16x2(a.w - bfhi_f(ph1), a.z - bflo_f(ph1));

    size_t base = (size_t)warp * IN_F + lane * 4;
    *reinterpret_cast<uint2*>(g_Ah + base) = make_uint2(ph0, ph1);
    *reinterpret_cast<uint2*>(g_Al + base) = make_uint2(pl0, pl1);
}

// ---------------------------------------------------------------------------
// Tensor-core MLP: out = relu(A@W1+b1)@W2 + b2, split-bf16 3-term MMA.
// Block = 64 rows / 4 warps. Warp owns 16 rows x 128 cols. Zero smem.
// ---------------------------------------------------------------------------
__global__ void __launch_bounds__(128)
k_mma(const float* __restrict__ b1, const float* __restrict__ b2,
      float* __restrict__ out, int N) {
    const int warp = threadIdx.x >> 5;
    const int lane = threadIdx.x & 31;
    const int g = lane >> 2;
    const int t = lane & 3;
    const int row0 = blockIdx.x * 64 + warp * 16;

    float c[16][4];

    // ---- GEMM1: C = A @ W1 + b1 ----
    #pragma unroll
    for (int nt = 0; nt < 16; nt++) {
        float v0 = b1[nt * 8 + 2 * t], v1 = b1[nt * 8 + 2 * t + 1];
        c[nt][0] = v0; c[nt][1] = v1; c[nt][2] = v0; c[nt][3] = v1;
    }

    {
        const size_t rA = (size_t)(row0 + g) * IN_F;
        const size_t rB = (size_t)(row0 + g + 8) * IN_F;
        #pragma unroll
        for (int ks = 0; ks < 8; ks++) {
            int col = ks * 16 + 2 * t;
            unsigned ah0 = *reinterpret_cast<const unsigned*>(g_Ah + rA + col);
            unsigned ah1 = *reinterpret_cast<const unsigned*>(g_Ah + rB + col);
            unsigned ah2 = *reinterpret_cast<const unsigned*>(g_Ah + rA + col + 8);
            unsigned ah3 = *reinterpret_cast<const unsigned*>(g_Ah + rB + col + 8);
            unsigned al0 = *reinterpret_cast<const unsigned*>(g_Al + rA + col);
            unsigned al1 = *reinterpret_cast<const unsigned*>(g_Al + rB + col);
            unsigned al2 = *reinterpret_cast<const unsigned*>(g_Al + rA + col + 8);
            unsigned al3 = *reinterpret_cast<const unsigned*>(g_Al + rB + col + 8);
            #pragma unroll
            for (int nt = 0; nt < 16; nt++) {
                int wb = (nt * 8 + g) * IN_F + ks * 16 + 2 * t;
                unsigned bh0 = *reinterpret_cast<const unsigned*>(g_W1h + wb);
                unsigned bh1 = *reinterpret_cast<const unsigned*>(g_W1h + wb + 8);
                unsigned bl0 = *reinterpret_cast<const unsigned*>(g_W1l + wb);
                unsigned bl1 = *reinterpret_cast<const unsigned*>(g_W1l + wb + 8);
                mma16816(c[nt], ah0, ah1, ah2, ah3, bh0, bh1);
                mma16816(c[nt], al0, al1, al2, al3, bh0, bh1);
                mma16816(c[nt], ah0, ah1, ah2, ah3, bl0, bl1);
            }
        }
    }

    // ---- relu + in-register split to GEMM2 A-fragments ----
    unsigned hh[16][2], hl[16][2];
    #pragma unroll
    for (int nt = 0; nt < 16; nt++) {
        float r0 = fmaxf(c[nt][0], 0.f), r1 = fmaxf(c[nt][1], 0.f);
        float r2 = fmaxf(c[nt][2], 0.f), r3 = fmaxf(c[nt][3], 0.f);
        unsigned p0 = cvt_bf16x2(r1, r0);
        unsigned p1 = cvt_bf16x2(r3, r2);
        hh[nt][0] = p0;
        hh[nt][1] = p1;
        hl[nt][0] = cvt_bf16x2(r1 - bfhi_f(p0), r0 - bflo_f(p0));
        hl[nt][1] = cvt_bf16x2(r3 - bfhi_f(p1), r2 - bflo_f(p1));
    }

    // ---- GEMM2: C = h @ W2 + b2 ----
    #pragma unroll
    for (int nt = 0; nt < 16; nt++) {
        float v0 = b2[nt * 8 + 2 * t], v1 = b2[nt * 8 + 2 * t + 1];
        c[nt][0] = v0; c[nt][1] = v1; c[nt][2] = v0; c[nt][3] = v1;
    }

    #pragma unroll
    for (int ks = 0; ks < 8; ks++) {
        unsigned ah0 = hh[2 * ks][0],     ah1 = hh[2 * ks][1];
        unsigned ah2 = hh[2 * ks + 1][0], ah3 = hh[2 * ks + 1][1];
        unsigned al0 = hl[2 * ks][0],     al1 = hl[2 * ks][1];
        unsigned al2 = hl[2 * ks + 1][0], al3 = hl[2 * ks + 1][1];
        #pragma unroll
        for (int nt = 0; nt < 16; nt++) {
            int wb = (nt * 8 + g) * IN_F + ks * 16 + 2 * t;
            unsigned bh0 = *reinterpret_cast<const unsigned*>(g_W2h + wb);
            unsigned bh1 = *reinterpret_cast<const unsigned*>(g_W2h + wb + 8);
            unsigned bl0 = *reinterpret_cast<const unsigned*>(g_W2l + wb);
            unsigned bl1 = *reinterpret_cast<const unsigned*>(g_W2l + wb + 8);
            mma16816(c[nt], ah0, ah1, ah2, ah3, bh0, bh1);
            mma16816(c[nt], al0, al1, al2, al3, bh0, bh1);
            mma16816(c[nt], ah0, ah1, ah2, ah3, bl0, bl1);
        }
    }

    // ---- epilogue ----
    int rowA = row0 + g, rowB = row0 + g + 8;
    #pragma unroll
    for (int nt = 0; nt < 16; nt++) {
        int colp = nt * 8 + 2 * t;
        if (rowA < N)
            *reinterpret_cast<float2*>(out + (size_t)rowA * IN_F + colp) =
                make_float2(c[nt][0], c[nt][1]);
        if (rowB < N)
            *reinterpret_cast<float2*>(out + (size_t)rowB * IN_F + colp) =
                make_float2(c[nt][2], c[nt][3]);
    }
}

// ---------------------------------------------------------------------------
extern "C" void kernel_launch(void* const* d_in, const int* in_sizes, int n_in,
                              void* d_out, int out_size) {
    const float* H  = (const float*)d_in[0];
    const void*  ei = d_in[1];
    const float* EA = (const float*)d_in[2];
    const float* We = (const float*)d_in[3];
    const float* be = (const float*)d_in[4];
    const float* W1 = (const float*)d_in[5];
    const float* b1 = (const float*)d_in[6];
    const float* W2 = (const float*)d_in[7];
    const float* b2 = (const float*)d_in[8];
    float* out = (float*)d_out;

    int N = in_sizes[0] / IN_F;
    int E = in_sizes[2] / EDGE_F;
    int nScanBlocks = (N + SCAN_BLK - 1) / SCAN_BLK;

    k_detect<<<1, 32>>>((const int*)ei);
    k_wsplit<<<(IN_F * IN_F + 255) / 256, 256>>>(W1, W2);
    k_zero<<<(N + 255) / 256, 256>>>(N);
    k_hist<<<(E + 255) / 256, 256>>>(ei, E);
    k_scanA<<<nScanBlocks, SCAN_BLK>>>(N);
    k_scanB<<<1, MAX_SCAN_BLOCKS>>>(nScanBlocks);
    k_initcur<<<(N + 255) / 256, 256>>>(N);
    k_scatter<<<(E + 255) / 256, 256>>>(ei, E);

    int gblocks = (N + 7) / 8;
    k_gather<<<gblocks, 256>>>(H, EA, We, be, N);

    k_mma<<<(N + 63) / 64, 128>>>(b1, b2, out, N);
}